// round 3
// baseline (speedup 1.0000x reference)
#include <cuda_runtime.h>

#define NQ      12
#define DIM     4096
#define NT      512         // threads per CTA
#define NR      8           // amplitudes per thread (DIM/NT)
#define NLAYERS 4
#define NGATES  60          // 12 encoding + 48 Rot

typedef unsigned long long u64;

// ---- packed f32x2 helpers (re in lo 32 bits, im in hi 32 bits) ----
__device__ __forceinline__ u64 pack2(float lo, float hi) {
    u64 r; asm("mov.b64 %0, {%1, %2};" : "=l"(r) : "f"(lo), "f"(hi)); return r;
}
__device__ __forceinline__ void unpack2(u64 v, float& lo, float& hi) {
    asm("mov.b64 {%0, %1}, %2;" : "=f"(lo), "=f"(hi) : "l"(v));
}
__device__ __forceinline__ u64 swap2(u64 v) {
    u64 r;
    asm("{\n\t.reg .b32 l, h;\n\tmov.b64 {l, h}, %1;\n\tmov.b64 %0, {h, l};\n\t}"
        : "=l"(r) : "l"(v));
    return r;
}
__device__ __forceinline__ u64 ffma2(u64 a, u64 b, u64 c) {
    u64 r; asm("fma.rn.f32x2 %0, %1, %2, %3;" : "=l"(r) : "l"(a), "l"(b), "l"(c)); return r;
}
__device__ __forceinline__ u64 fmul2(u64 a, u64 b) {
    u64 r; asm("mul.rn.f32x2 %0, %1, %2;" : "=l"(r) : "l"(a), "l"(b)); return r;
}

// Gate coefficient layout per gate in smem (8 u64):
//   [0]=A(u00) [1]=B(u00) [2]=A(u01) [3]=B(u01) [4]=A(u10) [5]=B(u10) [6]=A(u11) [7]=B(u11)
// where A(c)=(c.re,c.re), B(c)=(-c.im,c.im): complex mul c*m = A(c)*m + B(c)*swap(m).

// ---- gate on a register bit P (wires 9..11): pure register FMA ----
template<int P>
__device__ __forceinline__ void gate_reg(u64* st, const u64* g) {
    u64 A00=g[0],B00=g[1],A01=g[2],B01=g[3],A10=g[4],B10=g[5],A11=g[6],B11=g[7];
#pragma unroll
    for (int k = 0; k < NR / 2; k++) {
        const int r0 = ((k >> P) << (P + 1)) | (k & ((1 << P) - 1));
        const int r1 = r0 | (1 << P);
        u64 m0 = st[r0], m1 = st[r1];
        u64 s0 = swap2(m0), s1 = swap2(m1);
        u64 n0 = ffma2(A01, m1, ffma2(B01, s1, ffma2(B00, s0, fmul2(A00, m0))));
        u64 n1 = ffma2(A11, m1, ffma2(B11, s1, ffma2(B10, s0, fmul2(A10, m0))));
        st[r0] = n0; st[r1] = n1;
    }
}

// ---- gate on a lane bit LB (wires 4..8): shuffle exchange ----
template<int LB>
__device__ __forceinline__ void gate_lane(u64* st, const u64* g, int lane) {
    const int bit = (lane >> LB) & 1;
    u64 cAm = bit ? g[6] : g[0];
    u64 cBm = bit ? g[7] : g[1];
    u64 cAo = bit ? g[4] : g[2];
    u64 cBo = bit ? g[5] : g[3];
#pragma unroll
    for (int r = 0; r < NR; r++) {
        u64 o = __shfl_xor_sync(0xFFFFFFFFu, st[r], 1 << LB);
        u64 n = fmul2(cAm, st[r]);
        n = ffma2(cBm, swap2(st[r]), n);
        n = ffma2(cAo, o, n);
        n = ffma2(cBo, swap2(o), n);
        st[r] = n;
    }
}

// ---- gate on a thread bit TB (wires 0..3, TB in 5..8): smem exchange ----
template<int TB>
__device__ __forceinline__ void gate_warp(u64* st, const u64* g, int t, u64* xbuf) {
#pragma unroll
    for (int r = 0; r < NR; r++) xbuf[r * NT + t] = st[r];
    __syncthreads();
    const int pt  = t ^ (1 << TB);
    const int bit = (t >> TB) & 1;
    u64 cAm = bit ? g[6] : g[0];
    u64 cBm = bit ? g[7] : g[1];
    u64 cAo = bit ? g[4] : g[2];
    u64 cBo = bit ? g[5] : g[3];
#pragma unroll
    for (int r = 0; r < NR; r++) {
        u64 o = xbuf[r * NT + pt];
        u64 n = fmul2(cAm, st[r]);
        n = ffma2(cBm, swap2(st[r]), n);
        n = ffma2(cAo, o, n);
        n = ffma2(cBo, swap2(o), n);
        st[r] = n;
    }
    __syncthreads();
}

// ---- CNOT variants ----
template<int PC, int PT>
__device__ __forceinline__ void cnot_reg_rc(u64* st) {
#pragma unroll
    for (int r = 0; r < NR; r++) {
        if (((r >> PC) & 1) == 1 && ((r >> PT) & 1) == 0) {
            u64 tmp = st[r]; st[r] = st[r | (1 << PT)]; st[r | (1 << PT)] = tmp;
        }
    }
}
template<int PT>
__device__ __forceinline__ void cnot_reg_uc(u64* st, bool ctrl) {
    if (ctrl) {
#pragma unroll
        for (int r = 0; r < NR; r++) {
            if (((r >> PT) & 1) == 0) {
                u64 tmp = st[r]; st[r] = st[r | (1 << PT)]; st[r | (1 << PT)] = tmp;
            }
        }
    }
}
template<int LB>
__device__ __forceinline__ void cnot_lane(u64* st, bool ctrl) {
#pragma unroll
    for (int r = 0; r < NR; r++) {
        u64 o = __shfl_xor_sync(0xFFFFFFFFu, st[r], 1 << LB);
        if (ctrl) st[r] = o;
    }
}
template<int TB>
__device__ __forceinline__ void cnot_warp(u64* st, int t, bool ctrl, u64* xbuf) {
#pragma unroll
    for (int r = 0; r < NR; r++) xbuf[r * NT + t] = st[r];
    __syncthreads();
    const int pt = t ^ (1 << TB);
#pragma unroll
    for (int r = 0; r < NR; r++) {
        u64 o = xbuf[r * NT + pt];
        if (ctrl) st[r] = o;
    }
    __syncthreads();
}
// q=11: control = register bit 0 (wire 11), target = thread bit 8 (wire 0)
__device__ __forceinline__ void cnot_warp_rc(u64* st, int t, u64* xbuf) {
#pragma unroll
    for (int r = 1; r < NR; r += 2) xbuf[(r >> 1) * NT + t] = st[r];
    __syncthreads();
    const int pt = t ^ 256;
#pragma unroll
    for (int r = 1; r < NR; r += 2) st[r] = xbuf[(r >> 1) * NT + pt];
    __syncthreads();
}

// One sweep of 12 single-qubit gates (wires 0..11); gates on distinct wires commute.
// Layout: index bits 11..3 = thread bits t8..t0; bits 2..0 = reg bits.
// wire q <-> index bit (11-q):
//   wires 0-3 -> t8..t5 (warp bits), wires 4-8 -> t4..t0 (lane bits), wires 9-11 -> reg bits 2..0
__device__ __forceinline__ void apply_sweep(u64* st, const u64* G, int t, int lane, u64* xbuf) {
    gate_reg<2>(st, G +  9 * 8);    // wire 9
    gate_reg<1>(st, G + 10 * 8);    // wire 10
    gate_reg<0>(st, G + 11 * 8);    // wire 11
    gate_lane<4>(st, G + 4 * 8, lane);  // wire 4
    gate_lane<3>(st, G + 5 * 8, lane);  // wire 5
    gate_lane<2>(st, G + 6 * 8, lane);  // wire 6
    gate_lane<1>(st, G + 7 * 8, lane);  // wire 7
    gate_lane<0>(st, G + 8 * 8, lane);  // wire 8
    gate_warp<8>(st, G + 0 * 8, t, xbuf);  // wire 0
    gate_warp<7>(st, G + 1 * 8, t, xbuf);  // wire 1
    gate_warp<6>(st, G + 2 * 8, t, xbuf);  // wire 2
    gate_warp<5>(st, G + 3 * 8, t, xbuf);  // wire 3
}

__global__ void __launch_bounds__(NT)
qsim_kernel(const float* __restrict__ x,       // (B, 12)
            const float* __restrict__ w,       // (4, 12, 3)
            const float* __restrict__ ent,     // (4, 12)
            float* __restrict__ out)           // (B, 12)
{
    __shared__ u64   Usm[NGATES * 8];          // 3840 B gate coefficients
    __shared__ u64   xbuf[DIM];                // 32 KB exchange buffer
    __shared__ float red[(NT / 32) * NQ];

    const int b    = blockIdx.x;
    const int t    = threadIdx.x;
    const int lane = t & 31;

    // ---- precompute all 60 gate matrices (one thread per gate) ----
    if (t < NGATES) {
        const float PI = 3.14159265358979323846f;
        float2 u00, u01, u10, u11;
        if (t < NQ) {
            float xv = __ldg(&x[b * NQ + t]);
            float s, c;  sincosf(0.5f * PI * xv, &s, &c);
            float sh, ch; sincosf(0.5f * PI * xv * xv, &sh, &ch);
            u00 = make_float2( c * ch, -c * sh);
            u01 = make_float2(-s * ch,  s * sh);
            u10 = make_float2( s * ch,  s * sh);
            u11 = make_float2( c * ch,  c * sh);
        } else {
            int gi = t - NQ;   // = l*12 + q
            float phi = __ldg(&w[gi * 3 + 0]);
            float th  = __ldg(&w[gi * 3 + 1]);
            float om  = __ldg(&w[gi * 3 + 2]);
            float s, c;  sincosf(0.5f * th, &s, &c);
            float sp, cp; sincosf(0.5f * (om + phi), &sp, &cp);
            float sm, cm; sincosf(0.5f * (om - phi), &sm, &cm);
            u00 = make_float2( c * cp, -c * sp);
            u01 = make_float2(-s * cm,  s * sm);
            u10 = make_float2( s * cm,  s * sm);
            u11 = make_float2( c * cp,  c * sp);
        }
        u64* g = &Usm[t * 8];
        g[0] = pack2(u00.x, u00.x);  g[1] = pack2(-u00.y, u00.y);
        g[2] = pack2(u01.x, u01.x);  g[3] = pack2(-u01.y, u01.y);
        g[4] = pack2(u10.x, u10.x);  g[5] = pack2(-u10.y, u10.y);
        g[6] = pack2(u11.x, u11.x);  g[7] = pack2(-u11.y, u11.y);
    }
    __syncthreads();

    // ---- register-resident state: amplitude of index (t<<3)|r in st[r] ----
    u64 st[NR];
#pragma unroll
    for (int r = 0; r < NR; r++) st[r] = 0ULL;
    if (t == 0) st[0] = pack2(1.0f, 0.0f);

    // encoding sweep
    apply_sweep(st, Usm, t, lane, xbuf);

    // variational layers
    for (int l = 0; l < NLAYERS; l++) {
        apply_sweep(st, &Usm[(NQ + l * NQ) * 8], t, lane, xbuf);
        const float* el = &ent[l * NQ];
        // CNOT ring q -> q+1 (masks are CTA-uniform)
        if (__ldg(&el[0])  > 0.5f) cnot_warp<7>(st, t, (t >> 8) & 1, xbuf);  // c=w0,t=w1
        if (__ldg(&el[1])  > 0.5f) cnot_warp<6>(st, t, (t >> 7) & 1, xbuf);  // c=w1,t=w2
        if (__ldg(&el[2])  > 0.5f) cnot_warp<5>(st, t, (t >> 6) & 1, xbuf);  // c=w2,t=w3
        if (__ldg(&el[3])  > 0.5f) cnot_lane<4>(st, (t >> 5) & 1);           // c=w3,t=w4
        if (__ldg(&el[4])  > 0.5f) cnot_lane<3>(st, (lane >> 4) & 1);        // c=w4,t=w5
        if (__ldg(&el[5])  > 0.5f) cnot_lane<2>(st, (lane >> 3) & 1);        // c=w5,t=w6
        if (__ldg(&el[6])  > 0.5f) cnot_lane<1>(st, (lane >> 2) & 1);        // c=w6,t=w7
        if (__ldg(&el[7])  > 0.5f) cnot_lane<0>(st, (lane >> 1) & 1);        // c=w7,t=w8
        if (__ldg(&el[8])  > 0.5f) cnot_reg_uc<2>(st, lane & 1);             // c=w8,t=w9
        if (__ldg(&el[9])  > 0.5f) cnot_reg_rc<2, 1>(st);                    // c=w9,t=w10
        if (__ldg(&el[10]) > 0.5f) cnot_reg_rc<1, 0>(st);                    // c=w10,t=w11
        if (__ldg(&el[11]) > 0.5f) cnot_warp_rc(st, t, xbuf);                // c=w11,t=w0
    }

    // ---- readout: <Z_q> ----
    float psum = 0.f, a9 = 0.f, a10 = 0.f, a11 = 0.f;
#pragma unroll
    for (int r = 0; r < NR; r++) {
        float re, im; unpack2(st[r], re, im);
        float p = re * re + im * im;
        psum += p;
        a9  += ((r >> 2) & 1) ? -p : p;   // wire 9  (reg bit 2)
        a10 += ((r >> 1) & 1) ? -p : p;   // wire 10 (reg bit 1)
        a11 += ( r       & 1) ? -p : p;   // wire 11 (reg bit 0)
    }
    float acc[NQ];
#pragma unroll
    for (int q = 0; q < 9; q++)           // wires 0..8: sign from thread bit (8-q)
        acc[q] = ((t >> (8 - q)) & 1) ? -psum : psum;
    acc[9] = a9; acc[10] = a10; acc[11] = a11;

    const int wid = t >> 5;
#pragma unroll
    for (int q = 0; q < NQ; q++) {
        float v = acc[q];
#pragma unroll
        for (int o = 16; o; o >>= 1) v += __shfl_xor_sync(0xFFFFFFFFu, v, o);
        if (lane == 0) red[wid * NQ + q] = v;
    }
    __syncthreads();

    if (t < NQ) {
        float s = 0.f;
#pragma unroll
        for (int wi = 0; wi < NT / 32; wi++) s += red[wi * NQ + t];
        out[b * NQ + t] = s;   // SCALE = 1
    }
}

extern "C" void kernel_launch(void* const* d_in, const int* in_sizes, int n_in,
                              void* d_out, int out_size)
{
    const float* x   = (const float*)d_in[0];   // (B, 12)
    const float* w   = (const float*)d_in[1];   // (4, 12, 3)
    const float* ent = (const float*)d_in[2];   // (4, 12)
    float* out = (float*)d_out;                 // (B, 12)

    int B = in_sizes[0] / NQ;
    qsim_kernel<<<B, NT>>>(x, w, ent, out);
}

// round 4
// speedup vs baseline: 1.3044x; 1.3044x over previous
#include <cuda_runtime.h>

#define NQ      12
#define NT      256         // threads per CTA
#define NR      16          // amplitudes per thread
#define NLAYERS 4
#define NGATES  60          // 12 encoding + 48 Rot
#define XPITCH  17          // padded row pitch (u64) -> conflict-free transposes

typedef unsigned long long u64;

// ---- packed f32x2 helpers (re in lo 32 bits, im in hi 32 bits) ----
__device__ __forceinline__ u64 pack2(float lo, float hi) {
    u64 r; asm("mov.b64 %0, {%1, %2};" : "=l"(r) : "f"(lo), "f"(hi)); return r;
}
__device__ __forceinline__ void unpack2(u64 v, float& lo, float& hi) {
    asm("mov.b64 {%0, %1}, %2;" : "=f"(lo), "=f"(hi) : "l"(v));
}
__device__ __forceinline__ u64 swap2(u64 v) {
    u64 r;
    asm("{\n\t.reg .b32 l, h;\n\tmov.b64 {l, h}, %1;\n\tmov.b64 %0, {h, l};\n\t}"
        : "=l"(r) : "l"(v));
    return r;
}
__device__ __forceinline__ u64 ffma2(u64 a, u64 b, u64 c) {
    u64 r; asm("fma.rn.f32x2 %0, %1, %2, %3;" : "=l"(r) : "l"(a), "l"(b), "l"(c)); return r;
}
__device__ __forceinline__ u64 fmul2(u64 a, u64 b) {
    u64 r; asm("mul.rn.f32x2 %0, %1, %2;" : "=l"(r) : "l"(a), "l"(b)); return r;
}

// Gate coefficients per gate (8 u64): [A00 B00 A01 B01 A10 B10 A11 B11]
// A(c)=(re,re), B(c)=(-im,im): complex mul c*m = A*m + B*swap(m).

// ---- gate on register bit P: pure register FMA ----
template<int P>
__device__ __forceinline__ void gate_reg(u64* st, const u64* g) {
    ulonglong2 cA = *(const ulonglong2*)(g + 0);   // A00, B00
    ulonglong2 cB = *(const ulonglong2*)(g + 2);   // A01, B01
    ulonglong2 cC = *(const ulonglong2*)(g + 4);   // A10, B10
    ulonglong2 cD = *(const ulonglong2*)(g + 6);   // A11, B11
#pragma unroll
    for (int k = 0; k < NR / 2; k++) {
        const int r0 = ((k >> P) << (P + 1)) | (k & ((1 << P) - 1));
        const int r1 = r0 | (1 << P);
        u64 m0 = st[r0], m1 = st[r1];
        u64 s0 = swap2(m0), s1 = swap2(m1);
        st[r0] = ffma2(cB.x, m1, ffma2(cB.y, s1, ffma2(cA.y, s0, fmul2(cA.x, m0))));
        st[r1] = ffma2(cD.x, m1, ffma2(cD.y, s1, ffma2(cC.y, s0, fmul2(cC.x, m0))));
    }
}

// ======================= layouts & transposes =======================
// amp index bits [11..0]; thread bits t7..t0; register bits r3..r0.
// Layout A: idx = t7 t6 t5 t4 t3 t2 t1 t0 r3 r2 r1 r0
//           wires: w0..w7 = t7..t0 ; w8..w11 = r3..r0
// Layout C: idx = t7 t6 t5 t4 r3 r2 r1 r0 t3 t2 t1 t0   (swap r<->t3..t0)
//           wires: w0..w3 = t7..t4 ; w4..w7 = r3..r0 ; w8..w11 = t3..t0
// Layout D: idx = r3 r2 r1 r0 t7 t6 t5 t4 t3 t2 t1 t0   (from C, swap r<->t7..t4)
//           wires: w0..w3 = r3..r0 ; w4..w7 = t7..t4 ; w8..w11 = t3..t0
// phys(idx) = (idx>>4)*XPITCH + (idx&15)

// A->C: warp-local (swaps lane bits with reg bits)
__device__ __forceinline__ void exch_A_to_C(u64* st, int t, u64* xbuf) {
#pragma unroll
    for (int r = 0; r < NR; r++) xbuf[t * XPITCH + r] = st[r];
    __syncwarp();
    const int hi = (t >> 4) << 4;          // (wid<<5)|(t4<<4) as row-group base
    const int lo = t & 15;
#pragma unroll
    for (int r = 0; r < NR; r++) st[r] = xbuf[(hi | r) * XPITCH + lo];
    __syncwarp();
}
// C->A: warp-local (reverse)
__device__ __forceinline__ void exch_C_to_A(u64* st, int t, u64* xbuf) {
    const int hi = (t >> 4) << 4;
    const int lo = t & 15;
#pragma unroll
    for (int r = 0; r < NR; r++) xbuf[(hi | r) * XPITCH + lo] = st[r];
    __syncwarp();
#pragma unroll
    for (int r = 0; r < NR; r++) st[r] = xbuf[t * XPITCH + r];
    __syncwarp();
}
// C->D: cross-warp (swaps warp bits t7..t5 and t4 with reg bits)
__device__ __forceinline__ void exch_C_to_D(u64* st, int t, u64* xbuf) {
    const int hi = (t >> 4) << 4;
    const int lo = t & 15;
#pragma unroll
    for (int r = 0; r < NR; r++) xbuf[(hi | r) * XPITCH + lo] = st[r];
    __syncthreads();
    const int th = t >> 4;
#pragma unroll
    for (int r = 0; r < NR; r++) st[r] = xbuf[((r << 4) | th) * XPITCH + lo];
    __syncthreads();
}
// D->C: cross-warp (reverse)
__device__ __forceinline__ void exch_D_to_C(u64* st, int t, u64* xbuf) {
    const int th = t >> 4;
    const int lo = t & 15;
#pragma unroll
    for (int r = 0; r < NR; r++) xbuf[((r << 4) | th) * XPITCH + lo] = st[r];
    __syncthreads();
    const int hi = (t >> 4) << 4;
#pragma unroll
    for (int r = 0; r < NR; r++) st[r] = xbuf[(hi | r) * XPITCH + lo];
    __syncwarp();   // readers touched warp-local rows only; next writer is same-warp
}

// ======================= sweeps =======================
// gates for wires q at G + q*8
__device__ __forceinline__ void sweep_A_to_D(u64* st, const u64* G, int t, u64* xbuf) {
    gate_reg<3>(st, G +  8 * 8);   // w8
    gate_reg<2>(st, G +  9 * 8);   // w9
    gate_reg<1>(st, G + 10 * 8);   // w10
    gate_reg<0>(st, G + 11 * 8);   // w11
    exch_A_to_C(st, t, xbuf);
    gate_reg<3>(st, G +  4 * 8);   // w4
    gate_reg<2>(st, G +  5 * 8);   // w5
    gate_reg<1>(st, G +  6 * 8);   // w6
    gate_reg<0>(st, G +  7 * 8);   // w7
    exch_C_to_D(st, t, xbuf);
    gate_reg<3>(st, G +  0 * 8);   // w0
    gate_reg<2>(st, G +  1 * 8);   // w1
    gate_reg<1>(st, G +  2 * 8);   // w2
    gate_reg<0>(st, G +  3 * 8);   // w3
}
__device__ __forceinline__ void sweep_D_to_A(u64* st, const u64* G, int t, u64* xbuf) {
    gate_reg<3>(st, G +  0 * 8);   // w0
    gate_reg<2>(st, G +  1 * 8);   // w1
    gate_reg<1>(st, G +  2 * 8);   // w2
    gate_reg<0>(st, G +  3 * 8);   // w3
    exch_D_to_C(st, t, xbuf);
    gate_reg<3>(st, G +  4 * 8);   // w4
    gate_reg<2>(st, G +  5 * 8);   // w5
    gate_reg<1>(st, G +  6 * 8);   // w6
    gate_reg<0>(st, G +  7 * 8);   // w7
    exch_C_to_A(st, t, xbuf);
    gate_reg<3>(st, G +  8 * 8);   // w8
    gate_reg<2>(st, G +  9 * 8);   // w9
    gate_reg<1>(st, G + 10 * 8);   // w10
    gate_reg<0>(st, G + 11 * 8);   // w11
}

// ======================= CNOT primitives =======================
template<int PC, int PT>
__device__ __forceinline__ void cnot_reg_rc(u64* st) {
#pragma unroll
    for (int r = 0; r < NR; r++) {
        if (((r >> PC) & 1) == 1 && ((r >> PT) & 1) == 0) {
            u64 tmp = st[r]; st[r] = st[r | (1 << PT)]; st[r | (1 << PT)] = tmp;
        }
    }
}
template<int PT>
__device__ __forceinline__ void cnot_reg_uc(u64* st, bool ctrl) {
    if (ctrl) {
#pragma unroll
        for (int r = 0; r < NR; r++) {
            if (((r >> PT) & 1) == 0) {
                u64 tmp = st[r]; st[r] = st[r | (1 << PT)]; st[r | (1 << PT)] = tmp;
            }
        }
    }
}
template<int X>
__device__ __forceinline__ void cnot_lane(u64* st, bool ctrl) {
#pragma unroll
    for (int r = 0; r < NR; r++) {
        u64 o = __shfl_xor_sync(0xFFFFFFFFu, st[r], X);
        if (ctrl) st[r] = o;
    }
}
// ctrl = uniform warp-bit predicate (same on both partners), target = thread bit
template<int XORT>
__device__ __forceinline__ void cnot_cross(u64* st, int t, bool ctrl, u64* xbuf) {
    if (ctrl) {
#pragma unroll
        for (int r = 0; r < NR; r++) xbuf[t * XPITCH + r] = st[r];
    }
    __syncthreads();
    if (ctrl) {
        const int p = t ^ XORT;
#pragma unroll
        for (int r = 0; r < NR; r++) st[r] = xbuf[p * XPITCH + r];
    }
    __syncthreads();
}
// ctrl = reg bit 0, target = thread bit 7 (t^128): odd registers exchange
__device__ __forceinline__ void cnot_regctrl_t7(u64* st, int t, u64* xbuf) {
#pragma unroll
    for (int r = 1; r < NR; r += 2) xbuf[t * XPITCH + r] = st[r];
    __syncthreads();
    const int p = t ^ 128;
#pragma unroll
    for (int r = 1; r < NR; r += 2) st[r] = xbuf[p * XPITCH + r];
    __syncthreads();
}

__global__ void __launch_bounds__(NT)
qsim_kernel(const float* __restrict__ x,       // (B, 12)
            const float* __restrict__ w,       // (4, 12, 3)
            const float* __restrict__ ent,     // (4, 12)
            float* __restrict__ out)           // (B, 12)
{
    __shared__ __align__(16) u64 Usm[NGATES * 8];   // 3840 B gate coefficients
    __shared__ u64   xbuf[256 * XPITCH];            // 34816 B padded exchange buffer
    __shared__ float red[(NT / 32) * NQ];

    const int b    = blockIdx.x;
    const int t    = threadIdx.x;
    const int lane = t & 31;

    // ---- precompute all 60 gate matrices (one thread per gate) ----
    if (t < NGATES) {
        const float PI = 3.14159265358979323846f;
        float2 u00, u01, u10, u11;
        if (t < NQ) {
            float xv = __ldg(&x[b * NQ + t]);
            float s, c;  sincosf(0.5f * PI * xv, &s, &c);
            float sh, ch; sincosf(0.5f * PI * xv * xv, &sh, &ch);
            u00 = make_float2( c * ch, -c * sh);
            u01 = make_float2(-s * ch,  s * sh);
            u10 = make_float2( s * ch,  s * sh);
            u11 = make_float2( c * ch,  c * sh);
        } else {
            int gi = t - NQ;   // = l*12 + q
            float phi = __ldg(&w[gi * 3 + 0]);
            float th  = __ldg(&w[gi * 3 + 1]);
            float om  = __ldg(&w[gi * 3 + 2]);
            float s, c;  sincosf(0.5f * th, &s, &c);
            float sp, cp; sincosf(0.5f * (om + phi), &sp, &cp);
            float sm, cm; sincosf(0.5f * (om - phi), &sm, &cm);
            u00 = make_float2( c * cp, -c * sp);
            u01 = make_float2(-s * cm,  s * sm);
            u10 = make_float2( s * cm,  s * sm);
            u11 = make_float2( c * cp,  c * sp);
        }
        u64* g = &Usm[t * 8];
        g[0] = pack2(u00.x, u00.x);  g[1] = pack2(-u00.y, u00.y);
        g[2] = pack2(u01.x, u01.x);  g[3] = pack2(-u01.y, u01.y);
        g[4] = pack2(u10.x, u10.x);  g[5] = pack2(-u10.y, u10.y);
        g[6] = pack2(u11.x, u11.x);  g[7] = pack2(-u11.y, u11.y);
    }
    __syncthreads();

    // ---- register-resident state, layout A: amp (t<<4)|r in st[r] ----
    u64 st[NR];
#pragma unroll
    for (int r = 0; r < NR; r++) st[r] = 0ULL;
    if (t == 0) st[0] = pack2(1.0f, 0.0f);

    // encoding sweep: A -> D
    sweep_A_to_D(st, Usm, t, xbuf);

    // variational layers (layouts alternate D,A,D,A at CNOT time)
    for (int l = 0; l < NLAYERS; l++) {
        const u64* G = &Usm[(NQ + l * NQ) * 8];
        const float* el = &ent[l * NQ];
        if ((l & 1) == 0) {
            // state in D -> sweep D->A, CNOTs in layout A
            sweep_D_to_A(st, G, t, xbuf);
            // A: w0..w7 = t7..t0, w8..11 = r3..r0
            if (__ldg(&el[0])  > 0.5f) cnot_cross<64>(st, t, (t >> 7) & 1, xbuf);  // c=w0(t7), t=w1(t6)
            if (__ldg(&el[1])  > 0.5f) cnot_cross<32>(st, t, (t >> 6) & 1, xbuf);  // c=t6, t=t5
            if (__ldg(&el[2])  > 0.5f) cnot_lane<16>(st, (t >> 5) & 1);            // c=t5, t=t4
            if (__ldg(&el[3])  > 0.5f) cnot_lane<8>(st, (t >> 4) & 1);             // c=t4, t=t3
            if (__ldg(&el[4])  > 0.5f) cnot_lane<4>(st, (t >> 3) & 1);             // c=t3, t=t2
            if (__ldg(&el[5])  > 0.5f) cnot_lane<2>(st, (t >> 2) & 1);             // c=t2, t=t1
            if (__ldg(&el[6])  > 0.5f) cnot_lane<1>(st, (t >> 1) & 1);             // c=t1, t=t0
            if (__ldg(&el[7])  > 0.5f) cnot_reg_uc<3>(st, t & 1);                  // c=t0, t=r3
            if (__ldg(&el[8])  > 0.5f) cnot_reg_rc<3, 2>(st);                      // c=r3, t=r2
            if (__ldg(&el[9])  > 0.5f) cnot_reg_rc<2, 1>(st);                      // c=r2, t=r1
            if (__ldg(&el[10]) > 0.5f) cnot_reg_rc<1, 0>(st);                      // c=r1, t=r0
            if (__ldg(&el[11]) > 0.5f) cnot_regctrl_t7(st, t, xbuf);               // c=r0, t=t7
        } else {
            // state in A -> sweep A->D, CNOTs in layout D
            sweep_A_to_D(st, G, t, xbuf);
            // D: w0..3 = r3..r0, w4..7 = t7..t4, w8..11 = t3..t0
            if (__ldg(&el[0])  > 0.5f) cnot_reg_rc<3, 2>(st);                      // c=w0(r3), t=w1(r2)
            if (__ldg(&el[1])  > 0.5f) cnot_reg_rc<2, 1>(st);                      // c=r2, t=r1
            if (__ldg(&el[2])  > 0.5f) cnot_reg_rc<1, 0>(st);                      // c=r1, t=r0
            if (__ldg(&el[3])  > 0.5f) cnot_regctrl_t7(st, t, xbuf);               // c=r0, t=t7
            if (__ldg(&el[4])  > 0.5f) cnot_cross<64>(st, t, (t >> 7) & 1, xbuf);  // c=t7, t=t6
            if (__ldg(&el[5])  > 0.5f) cnot_cross<32>(st, t, (t >> 6) & 1, xbuf);  // c=t6, t=t5
            if (__ldg(&el[6])  > 0.5f) cnot_lane<16>(st, (t >> 5) & 1);            // c=t5, t=t4
            if (__ldg(&el[7])  > 0.5f) cnot_lane<8>(st, (t >> 4) & 1);             // c=t4, t=t3
            if (__ldg(&el[8])  > 0.5f) cnot_lane<4>(st, (t >> 3) & 1);             // c=t3, t=t2
            if (__ldg(&el[9])  > 0.5f) cnot_lane<2>(st, (t >> 2) & 1);             // c=t2, t=t1
            if (__ldg(&el[10]) > 0.5f) cnot_lane<1>(st, (t >> 1) & 1);             // c=t1, t=t0
            if (__ldg(&el[11]) > 0.5f) cnot_reg_uc<3>(st, t & 1);                  // c=t0, t=w0(r3)
        }
    }
    // NLAYERS=4: sequence D->A (l=0), A->D (l=1), D->A (l=2), A->D (l=3) -> final layout D

    // ---- readout in layout D: w0..3 = r3..r0, w4..11 = t7..t0 ----
    float psum = 0.f, a0 = 0.f, a1 = 0.f, a2 = 0.f, a3 = 0.f;
#pragma unroll
    for (int r = 0; r < NR; r++) {
        float re, im; unpack2(st[r], re, im);
        float p = re * re + im * im;
        psum += p;
        a0 += (r & 8) ? -p : p;
        a1 += (r & 4) ? -p : p;
        a2 += (r & 2) ? -p : p;
        a3 += (r & 1) ? -p : p;
    }
    float acc[NQ];
    acc[0] = a0; acc[1] = a1; acc[2] = a2; acc[3] = a3;
#pragma unroll
    for (int q = 4; q < NQ; q++)               // wires 4..11 -> thread bits t7..t0
        acc[q] = ((t >> (11 - q)) & 1) ? -psum : psum;

    const int wid = t >> 5;
#pragma unroll
    for (int q = 0; q < NQ; q++) {
        float v = acc[q];
#pragma unroll
        for (int o = 16; o; o >>= 1) v += __shfl_xor_sync(0xFFFFFFFFu, v, o);
        if (lane == 0) red[wid * NQ + q] = v;
    }
    __syncthreads();

    if (t < NQ) {
        float s = 0.f;
#pragma unroll
        for (int wi = 0; wi < NT / 32; wi++) s += red[wi * NQ + t];
        out[b * NQ + t] = s;   // SCALE = 1
    }
}

extern "C" void kernel_launch(void* const* d_in, const int* in_sizes, int n_in,
                              void* d_out, int out_size)
{
    const float* x   = (const float*)d_in[0];   // (B, 12)
    const float* w   = (const float*)d_in[1];   // (4, 12, 3)
    const float* ent = (const float*)d_in[2];   // (4, 12)
    float* out = (float*)d_out;                 // (B, 12)

    int B = in_sizes[0] / NQ;
    qsim_kernel<<<B, NT>>>(x, w, ent, out);
}